// round 6
// baseline (speedup 1.0000x reference)
#include <cuda_runtime.h>

// ---------------------------------------------------------------------------
// Threshold_weights7: per-row top-2 margins over 8 predictors [N,128],
// softmax(margins/2) over 8 predictors, plus global max of predictors 0..6.
// Memory-bound: 512MB read. FOUR rows per warp (8 lanes each); software-
// pipelined ping-pong loads (1 predictor per stage) so every compute phase
// covers an outstanding 4xLDG.128 burst. Single kernel, last-block finalize.
// ---------------------------------------------------------------------------

static constexpr int kC = 128;  // class dim

__device__ unsigned g_max_key;  // zero-init at load; self-reset every call
__device__ unsigned g_ticket;

__device__ __forceinline__ unsigned f2key(float f) {
    unsigned u = __float_as_uint(f);
    return (u & 0x80000000u) ? ~u : (u | 0x80000000u);
}

// (h,s) = top-2 of the 16 values in v[0..3]
__device__ __forceinline__ void top2_local(const float4* v, float& h, float& s) {
    float H[4], S[4];
#pragma unroll
    for (int i = 0; i < 4; i++) {
        float a1 = fmaxf(v[i].x, v[i].y), a2 = fminf(v[i].x, v[i].y);
        float b1 = fmaxf(v[i].z, v[i].w), b2 = fminf(v[i].z, v[i].w);
        H[i] = fmaxf(a1, b1);
        S[i] = fmaxf(fminf(a1, b1), fmaxf(a2, b2));
    }
    float h01 = fmaxf(H[0], H[1]), s01 = fmaxf(fminf(H[0], H[1]), fmaxf(S[0], S[1]));
    float h23 = fmaxf(H[2], H[3]), s23 = fmaxf(fminf(H[2], H[3]), fmaxf(S[2], S[3]));
    h = fmaxf(h01, h23);
    s = fmaxf(fminf(h01, h23), fmaxf(s01, s23));
}

__device__ __forceinline__ float sel4(float4 q, int tsub) {
    return (tsub == 0) ? q.x : (tsub == 1) ? q.y : (tsub == 2) ? q.z : q.w;
}

// margin for one predictor over a 4-row warp (8 lanes per row); also returns
// the row max via M1out.
__device__ __forceinline__ float pred_margin(const float4* v, int towner,
                                             int tq, int tsub, float& M1out) {
    float m1, m2;
    top2_local(v, m1, m2);

    // target logit: element tsub of float4 tq, from lane towner (within group)
    float c0 = sel4(v[0], tsub), c1 = sel4(v[1], tsub);
    float c2 = sel4(v[2], tsub), c3 = sel4(v[3], tsub);
    float tl = (tq == 0) ? c0 : (tq == 1) ? c1 : (tq == 2) ? c2 : c3;
    float tv = __shfl_sync(0xffffffffu, tl, towner, 8);

    // 3-step butterfly top-2 merge within the 8-lane group
#pragma unroll
    for (int off = 4; off; off >>= 1) {
        float o1 = __shfl_xor_sync(0xffffffffu, m1, off);
        float o2 = __shfl_xor_sync(0xffffffffu, m2, off);
        float n2 = fmaxf(fminf(m1, o1), fmaxf(m2, o2));
        m1 = fmaxf(m1, o1);
        m2 = n2;
    }
    M1out = m1;
    return (tv == m1) ? (m1 - m2) : 0.0f;  // exact tie semantics
}

__device__ __forceinline__ void ldrow(float4* dst, const float* __restrict__ p,
                                      size_t base) {
    const float4* src = reinterpret_cast<const float4*>(p + base);
#pragma unroll
    for (int i = 0; i < 4; i++) dst[i] = __ldcs(src + i);
}

__global__ void __launch_bounds__(256, 4)
k_main(const float* __restrict__ p0, const float* __restrict__ p1,
       const float* __restrict__ p2, const float* __restrict__ p3,
       const float* __restrict__ p4, const float* __restrict__ p5,
       const float* __restrict__ p6, const float* __restrict__ p7,
       const int* __restrict__ targets,
       float* __restrict__ out,   // [has_scalar + N*8]
       int nrows, int has_scalar)
{
    __shared__ unsigned s_gm[8];

    const int lane = threadIdx.x & 31;
    const int wib  = threadIdx.x >> 5;       // warp in block (0..7)
    const int grp  = lane >> 3;              // row group 0..3
    const int gl   = lane & 7;               // lane within group

    const int gwarp  = blockIdx.x * 8 + wib;
    const int nwarps = gridDim.x * 8;

    float* __restrict__ thr = out + has_scalar;
    const float* preds[8] = {p0, p1, p2, p3, p4, p5, p6, p7};

    float gm = -3.402823466e38f;  // running max over predictors 0..6

    const int nquads = (nrows + 3) >> 2;

    // ---- prologue: prefetch predictor 0 of the first quad ----
    float4 A[4], B[4];
    {
        int row0 = gwarp * 4 + grp;
        int rs = (row0 < nrows) ? row0 : (nrows - 1);
        ldrow(A, preds[0], (size_t)rs * kC + gl * 16);
    }

    for (int q = gwarp; q < nquads; q += nwarps) {
        const int row = q * 4 + grp;
        const bool rowok = (row < nrows);
        const int rsafe = rowok ? row : (nrows - 1);

        const int t = __ldg(targets + rsafe);
        const int towner = t >> 4;        // 16 floats per lane
        const int tq     = (t >> 2) & 3;  // which float4
        const int tsub   = t & 3;         // element within float4

        const size_t base = (size_t)rsafe * kC + gl * 16;

        // next-iteration base (safe address for tail)
        const int qn = q + nwarps;
        int rown = qn * 4 + grp;
        if (rown >= nrows) rown = nrows - 1;
        const size_t base_nxt = (size_t)rown * kC + gl * 16;

        float m[8], M1;

        // software pipeline: load pred p+1 while computing pred p
        ldrow(B, preds[1], base);
        m[0] = pred_margin(A, towner, tq, tsub, M1);
        if (rowok) gm = fmaxf(gm, M1);

        ldrow(A, preds[2], base);
        m[1] = pred_margin(B, towner, tq, tsub, M1);
        if (rowok) gm = fmaxf(gm, M1);

        ldrow(B, preds[3], base);
        m[2] = pred_margin(A, towner, tq, tsub, M1);
        if (rowok) gm = fmaxf(gm, M1);

        ldrow(A, preds[4], base);
        m[3] = pred_margin(B, towner, tq, tsub, M1);
        if (rowok) gm = fmaxf(gm, M1);

        ldrow(B, preds[5], base);
        m[4] = pred_margin(A, towner, tq, tsub, M1);
        if (rowok) gm = fmaxf(gm, M1);

        ldrow(A, preds[6], base);
        m[5] = pred_margin(B, towner, tq, tsub, M1);
        if (rowok) gm = fmaxf(gm, M1);

        ldrow(B, preds[7], base);
        m[6] = pred_margin(A, towner, tq, tsub, M1);
        if (rowok) gm = fmaxf(gm, M1);

        ldrow(A, preds[0], base_nxt);     // prefetch next quad's first batch
        m[7] = pred_margin(B, towner, tq, tsub, M1);   // mimic: no gm

        // softmax over 8 margins, T=2 (redundant within group; serves 4 rows)
        float mm = m[0];
#pragma unroll
        for (int p = 1; p < 8; p++) mm = fmaxf(mm, m[p]);
        float e[8], s = 0.0f;
#pragma unroll
        for (int p = 0; p < 8; p++) { e[p] = __expf((m[p] - mm) * 0.5f); s += e[p]; }
        const float inv = 1.0f / s;

        if (rowok) {
            float mine = (gl == 0) ? e[0] : (gl == 1) ? e[1]
                       : (gl == 2) ? e[2] : (gl == 3) ? e[3]
                       : (gl == 4) ? e[4] : (gl == 5) ? e[5]
                       : (gl == 6) ? e[6] : e[7];
            thr[(size_t)row * 8 + gl] = mine * inv;   // warp: dense 128B store
        }
    }

    // ---- global-max finalize (last-block ticket) ----
    gm = fmaxf(gm, __shfl_xor_sync(0xffffffffu, gm, 8));
    gm = fmaxf(gm, __shfl_xor_sync(0xffffffffu, gm, 16));
    if (lane == 0) s_gm[wib] = f2key(gm);
    __syncthreads();
    if (threadIdx.x == 0) {
        unsigned k = s_gm[0];
#pragma unroll
        for (int i = 1; i < 8; i++) k = max(k, s_gm[i]);
        atomicMax(&g_max_key, k);
        __threadfence();
        unsigned old = atomicAdd(&g_ticket, 1u);
        if (old == gridDim.x - 1) {
            unsigned kk = g_max_key;
            if (has_scalar) {
                unsigned u = (kk & 0x80000000u) ? (kk & 0x7FFFFFFFu) : ~kk;
                out[0] = __uint_as_float(u);
            }
            g_max_key = 0u;   // reset for next graph replay
            g_ticket  = 0u;
        }
    }
}

extern "C" void kernel_launch(void* const* d_in, const int* in_sizes, int n_in,
                              void* d_out, int out_size)
{
    const float* p[8];
    for (int i = 0; i < 8; i++) p[i] = (const float*)d_in[i];
    const int* targets = (const int*)d_in[8];
    const int nrows = in_sizes[8];           // targets element count == N

    float* out = (float*)d_out;
    int has_scalar = out_size - nrows * 8;
    if (has_scalar < 0) has_scalar = 0;

    k_main<<<2048, 256>>>(p[0], p[1], p[2], p[3], p[4], p[5], p[6], p[7],
                          targets, out, nrows, has_scalar);
}